// round 3
// baseline (speedup 1.0000x reference)
#include <cuda_runtime.h>
#include <cstdint>

// Problem constants (from reference)
#define TT   8192
#define BB   8
#define DD   512
#define NC   64          // number of chunks along T
#define CL   128         // chunk length = TT/NC
#define C0F  2.0f        // PRIOR_COUNT
#define EPSF 1e-5f

// Scratch: partial (then exclusive-prefix) sums per (chunk, b, d) and counts per (chunk, b).
__device__ float g_psx [NC * BB * DD];
__device__ float g_psxx[NC * BB * DD];
__device__ int   g_cnt [NC * BB];

// ---------------------------------------------------------------------------
// Kernel A: per-chunk partial sums of valid*x and valid*x^2, plus valid counts.
// grid = (NC, BB), block = DD threads (one per d).
// ---------------------------------------------------------------------------
__global__ void __launch_bounds__(DD) tn_partial(
    const float* __restrict__ x, const unsigned char* __restrict__ mask)
{
    const int chunk = blockIdx.x;
    const int b     = blockIdx.y;
    const int d     = threadIdx.x;

    const float* xp = x + ((size_t)(chunk * CL) * BB + b) * DD + d;
    const unsigned char* mp = mask + (size_t)b * TT + chunk * CL;
    const int stride = BB * DD;

    float sx = 0.0f, sxx = 0.0f;
#pragma unroll 4
    for (int t = 0; t < CL; ++t) {
        float v      = xp[(size_t)t * stride];
        float valid  = mp[t] ? 0.0f : 1.0f;
        float xv     = v * valid;
        sx  += xv;
        sxx  = fmaf(xv, v, sxx);
    }
    g_psx [(chunk * BB + b) * DD + d] = sx;
    g_psxx[(chunk * BB + b) * DD + d] = sxx;

    // valid count for this (chunk, b): threads 0..127 each own one t.
    __shared__ int scnt;
    if (threadIdx.x == 0) scnt = 0;
    __syncthreads();
    if (threadIdx.x < CL) {
        unsigned char m = mp[threadIdx.x];
        unsigned bal = __ballot_sync(0xFFFFFFFFu, m == 0);
        if ((threadIdx.x & 31) == 0) atomicAdd(&scnt, __popc(bal));
    }
    __syncthreads();
    if (threadIdx.x == 0) g_cnt[chunk * BB + b] = scnt;
}

// ---------------------------------------------------------------------------
// Kernel B: in-place exclusive scan across chunks (tiny; L2-resident).
// grid*block >= BB*DD threads; thread id = b*DD + d channel; threads < BB
// additionally scan the counts.
// ---------------------------------------------------------------------------
__global__ void tn_scan()
{
    const int id = blockIdx.x * blockDim.x + threadIdx.x;
    if (id < BB * DD) {
        float ax = 0.0f, axx = 0.0f;
#pragma unroll 8
        for (int c = 0; c < NC; ++c) {
            int i = c * BB * DD + id;
            float sx = g_psx[i], sxx = g_psxx[i];
            g_psx[i] = ax; g_psxx[i] = axx;
            ax += sx; axx += sxx;
        }
    }
    if (id < BB) {
        int acc = 0;
#pragma unroll 8
        for (int c = 0; c < NC; ++c) {
            int i = c * BB + id;
            int v = g_cnt[i];
            g_cnt[i] = acc;
            acc += v;
        }
    }
}

// ---------------------------------------------------------------------------
// Kernel C: final pass. Each thread carries (cf, P, Q) from its chunk's
// exclusive prefix and emits y for its 128 timesteps.
// grid = (NC, BB), block = DD.
// ---------------------------------------------------------------------------
__global__ void __launch_bounds__(DD) tn_final(
    const float* __restrict__ x,
    const float* __restrict__ prior_mean,
    const float* __restrict__ prior_logv,
    const float* __restrict__ weight,
    const float* __restrict__ bias,
    const unsigned char* __restrict__ mask,
    float* __restrict__ out)
{
    const int chunk = blockIdx.x;
    const int b     = blockIdx.y;
    const int d     = threadIdx.x;

    const float m0    = prior_mean[d];
    const float v0    = __expf(prior_logv[d]);
    const float gamma = weight[d] + 1.0f;
    const float beta  = bias[d];
    const float A     = C0F * m0;               // prior contribution to sum
    const float Bc    = C0F * fmaf(m0, m0, v0); // prior contribution to sum-of-squares

    const int ci = (chunk * BB + b) * DD + d;
    float P  = g_psx[ci];
    float Q  = g_psxx[ci];
    float cf = C0F + (float)g_cnt[chunk * BB + b];

    const int stride = BB * DD;
    const float* xp = x   + ((size_t)(chunk * CL) * BB + b) * DD + d;
    float*       op = (float*)out + ((size_t)(chunk * CL) * BB + b) * DD + d;
    const unsigned char* mp = mask + (size_t)b * TT + chunk * CL;

#pragma unroll 4
    for (int t = 0; t < CL; ++t) {
        float xv    = xp[(size_t)t * stride];
        float valid = mp[t] ? 0.0f : 1.0f;

        cf += valid;
        float xvv = xv * valid;
        P = fmaf(valid, xv, P);          // P += valid * x
        Q = fmaf(xvv, xv, Q);            // Q += valid * x^2

        float invc = __fdividef(1.0f, cf);       // MUFU.RCP path
        float mean = (A + P) * invc;
        float t2   = Q + Bc;
        float M2   = fmaf(-cf, mean * mean, t2); // M2 = (Q+Bc) - cf*mean^2
        float var  = M2 * invc;
        float rs   = rsqrtf(var + EPSF);         // MUFU.RSQ path
        float g2   = rs * gamma;
        op[(size_t)t * stride] = fmaf(xv - mean, g2, beta);
    }
}

// ---------------------------------------------------------------------------
// kernel_launch
// Inputs (metadata order): x, prior_mean, prior_logv, weight, bias, padding_mask
// ---------------------------------------------------------------------------
extern "C" void kernel_launch(void* const* d_in, const int* in_sizes, int n_in,
                              void* d_out, int out_size)
{
    const float* x          = (const float*)d_in[0];
    const float* prior_mean = (const float*)d_in[1];
    const float* prior_logv = (const float*)d_in[2];
    const float* weight     = (const float*)d_in[3];
    const float* bias       = (const float*)d_in[4];
    const unsigned char* mask = (const unsigned char*)d_in[5];
    float* out = (float*)d_out;

    dim3 grid(NC, BB);
    tn_partial<<<grid, DD>>>(x, mask);
    tn_scan<<<8, 512>>>();
    tn_final<<<grid, DD>>>(x, prior_mean, prior_logv, weight, bias, mask, out);
}